// round 3
// baseline (speedup 1.0000x reference)
#include <cuda_runtime.h>
#include <stdint.h>

#define VOCAB 100000
#define EMBED 64
#define KIDS  20
#define BROWS (1024 * 50)          // B*S output rows
#define ROWS_PER_BLOCK 16
#define THREADS 256                // 16 lanes per row * 16 rows

// Scratch: W transposed to [V, E]; each vocab row = contiguous 256 B.
// 100000 * 64 * 4 B = 25.6 MB (L2-resident; L2 = ~126 MB).
__device__ float4 g_Wt[VOCAB * EMBED / 4];

// ---------------------------------------------------------------------------
// Kernel 1: tiled transpose W[E, V] -> Wt[V, E]
// ---------------------------------------------------------------------------
__global__ void transpose_W_kernel(const float* __restrict__ W) {
    __shared__ float tile[32][33];
    const int v0 = blockIdx.x * 32;
    const int e0 = blockIdx.y * 32;
    const int tx = threadIdx.x;   // 0..31
    const int ty = threadIdx.y;   // 0..7

    #pragma unroll
    for (int j = 0; j < 4; j++) {
        tile[ty + 8 * j][tx] =
            W[(size_t)(e0 + ty + 8 * j) * VOCAB + (v0 + tx)];
    }
    __syncthreads();

    float* Wt = reinterpret_cast<float*>(g_Wt);
    #pragma unroll
    for (int j = 0; j < 4; j++) {
        Wt[(size_t)(v0 + ty + 8 * j) * EMBED + (e0 + tx)] = tile[tx][ty + 8 * j];
    }
}

// ---------------------------------------------------------------------------
// Kernel 2: gather-reduce.
// Block = 16 rows. Ids staged in smem with one coalesced pass, so the 20
// float4 gathers per thread are fully independent (max MLP, no id chain).
// Lane t of a row-group owns embed elements [4t, 4t+4).
// ---------------------------------------------------------------------------
__global__ __launch_bounds__(THREADS)
void gather_reduce_kernel(const int* __restrict__ ids,
                          const float* __restrict__ bias,
                          float* __restrict__ out) {
    __shared__ int s_ids[ROWS_PER_BLOCK * KIDS];   // 320 ints

    const int tid = threadIdx.x;
    const size_t block_id_base = (size_t)blockIdx.x * (ROWS_PER_BLOCK * KIDS);

    // Coalesced stage of all 320 ids for this block's 16 rows.
    #pragma unroll
    for (int i = tid; i < ROWS_PER_BLOCK * KIDS; i += THREADS) {
        s_ids[i] = __ldg(ids + block_id_base + i);
    }

    const int row_local = tid >> 4;      // 0..15
    const int lane      = tid & 15;      // 0..15

    // Bias: 16 distinct float4s, broadcast across rows -> L1-resident.
    float4 acc = __ldg(reinterpret_cast<const float4*>(bias) + lane);

    __syncthreads();

    // Pull the 20 ids (smem broadcast) then issue 20 independent LDG.128.
    int id[KIDS];
    #pragma unroll
    for (int k = 0; k < KIDS; k++) id[k] = s_ids[row_local * KIDS + k];

    #pragma unroll
    for (int k = 0; k < KIDS; k++) {
        const float4 w = __ldg(&g_Wt[(size_t)id[k] * 16 + lane]);
        acc.x += w.x; acc.y += w.y; acc.z += w.z; acc.w += w.w;
    }

    const size_t row = (size_t)blockIdx.x * ROWS_PER_BLOCK + row_local;
    reinterpret_cast<float4*>(out)[row * 16 + lane] = acc;
}

// ---------------------------------------------------------------------------
// Launch: inputs in metadata order: content_input (int32), W (f32), b (f32)
// ---------------------------------------------------------------------------
extern "C" void kernel_launch(void* const* d_in, const int* in_sizes, int n_in,
                              void* d_out, int out_size) {
    const int*   ids  = (const int*)  d_in[0];   // [B, S, K] int32
    const float* W    = (const float*)d_in[1];   // [E, V] f32
    const float* bias = (const float*)d_in[2];   // [E] f32
    float*       out  = (float*)d_out;           // [B, S, E] f32

    dim3 tgrid(VOCAB / 32, EMBED / 32);
    dim3 tblk(32, 8);
    transpose_W_kernel<<<tgrid, tblk>>>(W);

    const int blocks = BROWS / ROWS_PER_BLOCK;   // 3200
    gather_reduce_kernel<<<blocks, THREADS>>>(ids, bias, out);
}

// round 5
// speedup vs baseline: 1.2331x; 1.2331x over previous
#include <cuda_runtime.h>
#include <cuda_fp16.h>
#include <stdint.h>

#define VOCAB 100000
#define EMBED 64
#define KIDS  20
#define BROWS (1024 * 50)          // B*S output rows

// Wt in fp16, [V, E]: each vocab row = 64 halves = 128 B = ONE L2 line.
// Total 12.8 MB — comfortably L2-resident (126 MB L2).
__device__ __half g_Wt[VOCAB * EMBED];

// ---------------------------------------------------------------------------
// Kernel 1: tiled transpose + downconvert  W[E,V] f32 -> Wt[V,E] f16
// Grid (V/32, E/32), block 256. Read coalesced along V, write half2 along E.
// ---------------------------------------------------------------------------
__global__ __launch_bounds__(256)
void transpose_W_kernel(const float* __restrict__ W) {
    __shared__ float tile[32][33];
    const int v0 = blockIdx.x * 32;
    const int e0 = blockIdx.y * 32;
    const int tx = threadIdx.x & 31;
    const int ty = threadIdx.x >> 5;   // 0..7

    // Coalesced read along V: tile[e_local][v_local]
    #pragma unroll
    for (int j = 0; j < 4; j++) {
        tile[ty + 8 * j][tx] =
            W[(size_t)(e0 + ty + 8 * j) * VOCAB + (v0 + tx)];
    }
    __syncthreads();

    // Write phase: 32 v-rows x 16 half2 (=32 e) per tile = 512 half2.
    // 256 threads -> 2 each; consecutive threads hit consecutive half2.
    __half2* WtH2 = reinterpret_cast<__half2*>(g_Wt);
    const int tid = threadIdx.x;
    #pragma unroll
    for (int r = 0; r < 2; r++) {
        const int idx  = tid + r * 256;
        const int vrow = idx >> 4;          // 0..31
        const int c    = idx & 15;          // half2 col within 32-e block
        const float2 f = make_float2(tile[2 * c][vrow], tile[2 * c + 1][vrow]);
        WtH2[(size_t)(v0 + vrow) * (EMBED / 2) + (e0 >> 1) + c] =
            __float22half2_rn(f);
    }
}

// ---------------------------------------------------------------------------
// Kernel 2: gather-reduce. 8 lanes per row (lane owns 8 embeds), 32 rows/block.
// Each gather = LDG.128 of 8 halves; warp reads 4 rows = 4 x 128B lines.
// fp32 accumulation.
// ---------------------------------------------------------------------------
#define ROWS_PER_BLOCK 32
#define THREADS 256

__global__ __launch_bounds__(THREADS)
void gather_reduce_kernel(const int* __restrict__ ids,
                          const float* __restrict__ bias,
                          float* __restrict__ out) {
    __shared__ int s_ids[ROWS_PER_BLOCK * KIDS];   // 640 ints

    const int tid = threadIdx.x;
    const size_t block_id_base = (size_t)blockIdx.x * (ROWS_PER_BLOCK * KIDS);

    // Coalesced stage of this block's 640 ids.
    #pragma unroll
    for (int i = tid; i < ROWS_PER_BLOCK * KIDS; i += THREADS) {
        s_ids[i] = __ldg(ids + block_id_base + i);
    }

    const int row_local = tid >> 3;     // 0..31
    const int lane      = tid & 7;      // 0..7, owns e in [8*lane, 8*lane+8)

    // Bias: 8 floats per lane, broadcast across rows (L1-resident).
    const float4 b0 = __ldg(reinterpret_cast<const float4*>(bias) + 2 * lane);
    const float4 b1 = __ldg(reinterpret_cast<const float4*>(bias) + 2 * lane + 1);
    float acc[8] = { b0.x, b0.y, b0.z, b0.w, b1.x, b1.y, b1.z, b1.w };

    __syncthreads();

    int id[KIDS];
    #pragma unroll
    for (int k = 0; k < KIDS; k++) id[k] = s_ids[row_local * KIDS + k];

    const float4* WtV = reinterpret_cast<const float4*>(g_Wt);  // 16B = 8 halves

    #pragma unroll
    for (int k = 0; k < KIDS; k++) {
        // row byte base = id*128; lane picks 16B chunk -> float4 of 4 half2
        const float4 raw = __ldg(&WtV[(size_t)id[k] * 8 + lane]);
        const __half2* h = reinterpret_cast<const __half2*>(&raw);
        #pragma unroll
        for (int p = 0; p < 4; p++) {
            const float2 f = __half22float2(h[p]);
            acc[2 * p]     += f.x;
            acc[2 * p + 1] += f.y;
        }
    }

    // Output: lane writes 8 floats = 32 B; warp's 4 rows are contiguous.
    const size_t row = (size_t)blockIdx.x * ROWS_PER_BLOCK + row_local;
    float4* o = reinterpret_cast<float4*>(out + row * EMBED + lane * 8);
    o[0] = make_float4(acc[0], acc[1], acc[2], acc[3]);
    o[1] = make_float4(acc[4], acc[5], acc[6], acc[7]);
}

// ---------------------------------------------------------------------------
// Launch: inputs in metadata order: content_input (int32), W (f32), b (f32)
// ---------------------------------------------------------------------------
extern "C" void kernel_launch(void* const* d_in, const int* in_sizes, int n_in,
                              void* d_out, int out_size) {
    const int*   ids  = (const int*)  d_in[0];   // [B, S, K] int32
    const float* W    = (const float*)d_in[1];   // [E, V] f32
    const float* bias = (const float*)d_in[2];   // [E] f32
    float*       out  = (float*)d_out;           // [B, S, E] f32

    dim3 tgrid(VOCAB / 32, EMBED / 32);          // (3125, 2)
    transpose_W_kernel<<<tgrid, 256>>>(W);

    const int blocks = BROWS / ROWS_PER_BLOCK;   // 1600
    gather_reduce_kernel<<<blocks, THREADS>>>(ids, bias, out);
}